// round 16
// baseline (speedup 1.0000x reference)
#include <cuda_runtime.h>
#include <cuda_fp16.h>
#include <math.h>

#define Bn 16384
#define Dn 1024
#define Hn 4096
#define MAXK 72
#define MAXA 544

// ---- output layout (elements, fp32) ----
static const size_t OFF_LATK   = 0ULL;
static const size_t OFF_XB     = (size_t)Bn * Hn;
static const size_t OFF_PREM2  = OFF_XB + (size_t)Bn * Dn;
static const size_t OFF_LAT4K  = OFF_PREM2 + (size_t)Bn * Hn;
static const size_t OFF_LATAUX = OFF_LAT4K + (size_t)Bn * Hn;
static const size_t OFF_RECK   = OFF_LATAUX + (size_t)Bn * Hn;
static const size_t OFF_REC4K  = OFF_RECK + (size_t)Bn * Dn;
static const size_t OFF_RECAUX = OFF_REC4K + (size_t)Bn * Dn;
static const size_t OFF_RECKPB = OFF_RECAUX + (size_t)Bn * Dn;
static const size_t OFF_STATS  = OFF_RECKPB + (size_t)Bn * Dn;

// ---- device scratch ----
__device__ float    g_pre[(size_t)Bn * Hn];       // 256 MB
__device__ int      g_hits1[Hn];
__device__ int      g_hits2[Hn];
__device__ int      g_stats1[Hn];
__device__ unsigned g_dead1[Hn / 32];
__device__ unsigned g_dead12[Hn / 32];
__device__ int      g_kcnt[Bn];
__device__ int      g_kidx[(size_t)Bn * MAXK];
__device__ float    g_kval[(size_t)Bn * MAXK];
__device__ int      g_acnt[Bn];
__device__ int      g_aidx[(size_t)Bn * MAXA];
__device__ float    g_aval[(size_t)Bn * MAXA];

// fp16 limb matrices, row-major. limb1 scaled by 2^11 (normal range)
__device__ __align__(16) half gA0[(size_t)Bn * Dn];   // 32 MB
__device__ __align__(16) half gA1[(size_t)Bn * Dn];
__device__ __align__(16) half gB0[(size_t)Hn * Dn];   // 8 MB
__device__ __align__(16) half gB1[(size_t)Hn * Dn];

#define LIMB_SCALE 2048.0f
#define LIMB_INV   (1.0f / 2048.0f)

__device__ __forceinline__ unsigned fkey(float f) {
    unsigned u = __float_as_uint(f);
    return (u & 0x80000000u) ? ~u : (u | 0x80000000u);
}
__device__ __forceinline__ float funkey(unsigned k) {
    unsigned u = (k & 0x80000000u) ? (k ^ 0x80000000u) : ~k;
    return __uint_as_float(u);
}
__device__ __forceinline__ unsigned smem_u32(const void* p) {
    unsigned a;
    asm("{ .reg .u64 t; cvta.to.shared.u64 t, %1; cvt.u32.u64 %0, t; }" : "=r"(a) : "l"(p));
    return a;
}

// ---------------------------------------------------------------------------
__global__ void k_init() {
    int i = blockIdx.x * 256 + threadIdx.x;
    if (i < Hn) { g_hits1[i] = 0; g_hits2[i] = 0; }
}

// ---------------------------------------------------------------------------
// prepA: xb = x - pre_bias (output) + fp16 2-limb decomposition (limb1 * 2^11)
// ---------------------------------------------------------------------------
__global__ void k_prepA(const float* __restrict__ x, const float* __restrict__ pb,
                        float* __restrict__ xb_out) {
    unsigned g  = blockIdx.x * 256 + threadIdx.x;   // Bn*Dn/8 units of 8 elems
    unsigned kc = g & 127;
    size_t base = (size_t)g * 8;
    float v[8];
    float4 x0 = *(const float4*)(x + base);
    float4 x1 = *(const float4*)(x + base + 4);
    float4 p0 = *(const float4*)(pb + kc * 8);
    float4 p1 = *(const float4*)(pb + kc * 8 + 4);
    v[0] = x0.x - p0.x; v[1] = x0.y - p0.y; v[2] = x0.z - p0.z; v[3] = x0.w - p0.w;
    v[4] = x1.x - p1.x; v[5] = x1.y - p1.y; v[6] = x1.z - p1.z; v[7] = x1.w - p1.w;
    *(float4*)(xb_out + base)     = make_float4(v[0], v[1], v[2], v[3]);
    *(float4*)(xb_out + base + 4) = make_float4(v[4], v[5], v[6], v[7]);

    half h0[8], h1[8];
#pragma unroll
    for (int i = 0; i < 8; i++) {
        h0[i] = __float2half_rn(v[i]);
        h1[i] = __float2half_rn((v[i] - __half2float(h0[i])) * LIMB_SCALE);
    }
    *(uint4*)(gA0 + base) = *(const uint4*)h0;
    *(uint4*)(gA1 + base) = *(const uint4*)h1;
}

// ---------------------------------------------------------------------------
// prepB: W fp16 2-limb decomposition (limb1 * 2^11)
// ---------------------------------------------------------------------------
__global__ void k_prepB(const float* __restrict__ W) {
    unsigned g  = blockIdx.x * 256 + threadIdx.x;   // Hn*Dn/8
    size_t base = (size_t)g * 8;
    float v[8];
    float4 x0 = *(const float4*)(W + base);
    float4 x1 = *(const float4*)(W + base + 4);
    v[0] = x0.x; v[1] = x0.y; v[2] = x0.z; v[3] = x0.w;
    v[4] = x1.x; v[5] = x1.y; v[6] = x1.z; v[7] = x1.w;
    half h0[8], h1[8];
#pragma unroll
    for (int i = 0; i < 8; i++) {
        h0[i] = __float2half_rn(v[i]);
        h1[i] = __float2half_rn((v[i] - __half2float(h0[i])) * LIMB_SCALE);
    }
    *(uint4*)(gB0 + base) = *(const uint4*)h0;
    *(uint4*)(gB1 + base) = *(const uint4*)h1;
}

// ---------------------------------------------------------------------------
// HMMA GEMM: pre = xb @ W^T + latent_bias
// dual-accumulator limb scheme: C0 += a0b0 ; C1 += a0*b1s + a1s*b0
// 128x128x32 CTA tile, 256 threads (2x4 warps, 64x32 per warp)
// 5-stage cp.async pipeline, ONE barrier per chunk
// smem rows padded to 80B (conflict-free ldmatrix)
// ---------------------------------------------------------------------------
#define BK 32
#define NSTAGE 5
#define STAGE_B 40960                 // 4 slabs x 128 rows x 80B
#define SLAB_B 10240
#define NCH (Dn / BK)                 // 32

__device__ __forceinline__ void ldsm_x4(unsigned* r, unsigned addr) {
    asm volatile("ldmatrix.sync.aligned.m8n8.x4.shared.b16 {%0,%1,%2,%3}, [%4];"
                 : "=r"(r[0]), "=r"(r[1]), "=r"(r[2]), "=r"(r[3]) : "r"(addr));
}
__device__ __forceinline__ void ldsm_x2(unsigned* r, unsigned addr) {
    asm volatile("ldmatrix.sync.aligned.m8n8.x2.shared.b16 {%0,%1}, [%2];"
                 : "=r"(r[0]), "=r"(r[1]) : "r"(addr));
}
__device__ __forceinline__ void mma16816(float* c, const unsigned* a, const unsigned* b) {
    asm volatile("mma.sync.aligned.m16n8k16.row.col.f32.f16.f16.f32 "
                 "{%0,%1,%2,%3},{%4,%5,%6,%7},{%8,%9},{%0,%1,%2,%3};"
                 : "+f"(c[0]), "+f"(c[1]), "+f"(c[2]), "+f"(c[3])
                 : "r"(a[0]), "r"(a[1]), "r"(a[2]), "r"(a[3]), "r"(b[0]), "r"(b[1]));
}

__global__ __launch_bounds__(256, 1)
void k_mma(const float* __restrict__ lb) {
    extern __shared__ __align__(16) char smem[];
    const unsigned sb = smem_u32(smem);
    const int tid = threadIdx.x;
    const int wid = tid >> 5, lane = tid & 31;
    const int brow = blockIdx.y * 128, bcol = blockIdx.x * 128;
    const int wm = (wid >> 2) * 64, wn = (wid & 3) * 32;   // 2x4 warp grid

    float c0[4][4][4], c1[4][4][4];
#pragma unroll
    for (int i = 0; i < 4; i++)
#pragma unroll
        for (int j = 0; j < 4; j++)
#pragma unroll
            for (int q = 0; q < 4; q++) { c0[i][j][q] = 0.f; c1[i][j][q] = 0.f; }

    // load mapping: thread handles row r for all 4 slabs, 2x16B per slab
    const int r = tid >> 1, ub = (tid & 1) * 2;   // r 0..127, ub 0 or 2
    const half* sA0 = gA0 + (size_t)(brow + r) * Dn + ub * 8;
    const half* sA1 = gA1 + (size_t)(brow + r) * Dn + ub * 8;
    const half* sB0 = gB0 + (size_t)(bcol + r) * Dn + ub * 8;
    const half* sB1 = gB1 + (size_t)(bcol + r) * Dn + ub * 8;
    const unsigned dstb = r * 80 + ub * 16;

    auto ld_stage = [&](int c, int s) {
        unsigned d = sb + s * STAGE_B + dstb;
        const int co = c * BK;
        asm volatile("cp.async.cg.shared.global [%0], [%1], 16;" :: "r"(d),                  "l"(sA0 + co));
        asm volatile("cp.async.cg.shared.global [%0], [%1], 16;" :: "r"(d + 16),             "l"(sA0 + co + 8));
        asm volatile("cp.async.cg.shared.global [%0], [%1], 16;" :: "r"(d + SLAB_B),         "l"(sA1 + co));
        asm volatile("cp.async.cg.shared.global [%0], [%1], 16;" :: "r"(d + SLAB_B + 16),    "l"(sA1 + co + 8));
        asm volatile("cp.async.cg.shared.global [%0], [%1], 16;" :: "r"(d + 2 * SLAB_B),     "l"(sB0 + co));
        asm volatile("cp.async.cg.shared.global [%0], [%1], 16;" :: "r"(d + 2 * SLAB_B + 16),"l"(sB0 + co + 8));
        asm volatile("cp.async.cg.shared.global [%0], [%1], 16;" :: "r"(d + 3 * SLAB_B),     "l"(sB1 + co));
        asm volatile("cp.async.cg.shared.global [%0], [%1], 16;" :: "r"(d + 3 * SLAB_B + 16),"l"(sB1 + co + 8));
        asm volatile("cp.async.commit_group;" ::: "memory");
    };

    // prologue: 4 stages in flight
    ld_stage(0, 0); ld_stage(1, 1); ld_stage(2, 2); ld_stage(3, 3);

    const unsigned aoff = (wm + (lane & 15)) * 80 + (lane >> 4) * 16;
    const unsigned boff = (wn + (lane & 7)) * 80 + ((lane >> 3) & 1) * 16;

    for (int ch = 0; ch < NCH; ch++) {
        int s = ch % NSTAGE;
        asm volatile("cp.async.wait_group 3;" ::: "memory");
        __syncthreads();   // single barrier: stage s ready AND all warps done with stage (ch-1)%5
        if (ch + 4 < NCH) ld_stage(ch + 4, (ch + 4) % NSTAGE);
        else asm volatile("cp.async.commit_group;" ::: "memory");

        unsigned sbase = sb + s * STAGE_B;
#pragma unroll
        for (int ks = 0; ks < 2; ks++) {
            unsigned kb = ks * 32;
            unsigned a0f[4][4], a1f[4][4], b0f[4][2], b1f[4][2];
#pragma unroll
            for (int mf = 0; mf < 4; mf++) {
                unsigned ad = sbase + aoff + mf * (16 * 80) + kb;
                ldsm_x4(a0f[mf], ad);
                ldsm_x4(a1f[mf], ad + SLAB_B);
            }
#pragma unroll
            for (int nf = 0; nf < 4; nf++) {
                unsigned bd = sbase + 2 * SLAB_B + boff + nf * (8 * 80) + kb;
                ldsm_x2(b0f[nf], bd);
                ldsm_x2(b1f[nf], bd + SLAB_B);
            }
#pragma unroll
            for (int mf = 0; mf < 4; mf++)
#pragma unroll
                for (int nf = 0; nf < 4; nf++) {
                    mma16816(c0[mf][nf], a0f[mf], b0f[nf]);
                    mma16816(c1[mf][nf], a0f[mf], b1f[nf]);
                    mma16816(c1[mf][nf], a1f[mf], b0f[nf]);
                }
        }
    }

    // epilogue: combine limb accumulators, add bias, write g_pre
#pragma unroll
    for (int mf = 0; mf < 4; mf++) {
        int row0 = brow + wm + mf * 16 + (lane >> 2);
#pragma unroll
        for (int nf = 0; nf < 4; nf++) {
            int col = bcol + wn + nf * 8 + (lane & 3) * 2;
            float2 bv = *(const float2*)(lb + col);
            float2 v0, v1;
            v0.x = fmaf(c1[mf][nf][0], LIMB_INV, c0[mf][nf][0]) + bv.x;
            v0.y = fmaf(c1[mf][nf][1], LIMB_INV, c0[mf][nf][1]) + bv.y;
            v1.x = fmaf(c1[mf][nf][2], LIMB_INV, c0[mf][nf][2]) + bv.x;
            v1.y = fmaf(c1[mf][nf][3], LIMB_INV, c0[mf][nf][3]) + bv.y;
            *(float2*)(g_pre + (size_t)row0 * Hn + col)       = v0;
            *(float2*)(g_pre + (size_t)(row0 + 8) * Hn + col) = v1;
        }
    }
}

// ---------------------------------------------------------------------------
// suffix scan over a 256-bin histogram (warp shuffles, 2 barriers)
// ---------------------------------------------------------------------------
__device__ __forceinline__ int suffix_scan_p(int* hist, int* scan, int* wsum, int tid) {
    int w = tid >> 5, lane = tid & 31;
    int v = hist[tid];
#pragma unroll
    for (int off = 1; off < 32; off <<= 1) {
        int o = __shfl_down_sync(0xFFFFFFFFu, v, off);
        if (lane + off < 32) v += o;
    }
    if (lane == 0) wsum[w] = v;
    __syncthreads();
    int carry = 0;
#pragma unroll
    for (int w2 = 1; w2 < 8; w2++) carry += (w2 > w) ? wsum[w2] : 0;
    int ge = v + carry;
    scan[tid] = ge;
    __syncthreads();
    return ge;
}

// ---------------------------------------------------------------------------
// sel64: keys live in registers (16/thread), 4 radix passes from registers
// ---------------------------------------------------------------------------
struct Sel64Shared {
    int hist[256];
    int scan[256];
    int wsum[8];
    int bbin, bkk, cnt;
};

__global__ __launch_bounds__(256, 5)
void k_sel64(float* __restrict__ latk) {
    __shared__ Sel64Shared s;
    const int r = blockIdx.x, tid = threadIdx.x;
    const float* row = g_pre + (size_t)r * Hn;

    unsigned k[16];
#pragma unroll
    for (int j = 0; j < 16; j++) k[j] = fkey(row[tid + j * 256]);
    if (tid == 0) s.cnt = 0;

    unsigned prefix = 0, mask = 0;
    int kk = 64;
#pragma unroll
    for (int shift = 24; shift >= 0; shift -= 8) {
        s.hist[tid] = 0;
        __syncthreads();
#pragma unroll
        for (int j = 0; j < 16; j++) {
            unsigned u = k[j];
            if ((u & mask) == prefix) atomicAdd(&s.hist[(u >> shift) & 255], 1);
        }
        __syncthreads();
        int ge = suffix_scan_p(s.hist, s.scan, s.wsum, tid);
        int gt = (tid < 255) ? s.scan[tid + 1] : 0;
        if (ge >= kk && gt < kk) { s.bbin = tid; s.bkk = kk - gt; }
        __syncthreads();
        prefix |= ((unsigned)s.bbin) << shift;
        mask   |= 0xFFu << shift;
        kk = s.bkk;
    }
    const unsigned t64 = prefix;

    float* orow = latk + (size_t)r * Hn;
#pragma unroll
    for (int j = 0; j < 16; j++) {
        int i = tid + j * 256;
        unsigned u = k[j];
        bool sel = (u >= t64);
        float v = funkey(u);
        orow[i] = sel ? fmaxf(v, 0.f) : 0.f;
        if (sel) {
            if (v > 1e-5f) g_hits1[i] = 1;
            if (v > 0.f) {
                int p = atomicAdd(&s.cnt, 1);
                if (p < MAXK) {
                    g_kidx[(size_t)r * MAXK + p] = i;
                    g_kval[(size_t)r * MAXK + p] = v;
                }
            }
        }
    }
    __syncthreads();
    if (tid == 0) g_kcnt[r] = (s.cnt < MAXK) ? s.cnt : MAXK;
}

__global__ void k_stats1(const int* __restrict__ stats_in) {
    int h = blockIdx.x * 256 + threadIdx.x;
    int s1 = g_hits1[h] ? 1 : stats_in[h] + 1;
    g_stats1[h] = s1;
    unsigned b = __ballot_sync(0xFFFFFFFFu, s1 > 30);
    if ((threadIdx.x & 31) == 0) g_dead1[h >> 5] = b;
}

// ---------------------------------------------------------------------------
// selaux: degenerate fast path (all-dead mask) + full smem-based live path
// ---------------------------------------------------------------------------
struct SelShared {
    unsigned su[Hn];
    int hist[256];
    int scan[256];
    int wsum[8];
    int bbin, bkk, bbin2, bkk2, cnt, anylive;
};

// dual-k radix select: shares histogram passes while prefixes agree
__device__ void radix_kth2(SelShared* s, int kA0, int kB0,
                           unsigned* tA, unsigned* tB) {
    const int tid = threadIdx.x;
    unsigned prefA = 0, prefB = 0, mask = 0;
    int kkA = kA0, kkB = kB0;
#pragma unroll
    for (int shift = 24; shift >= 0; shift -= 8) {
        bool same = (prefA == prefB);
        s->hist[tid] = 0;
        __syncthreads();
        for (int i = tid; i < Hn; i += 256) {
            unsigned u = s->su[i];
            if ((u & mask) == prefA) atomicAdd(&s->hist[(u >> shift) & 255], 1);
        }
        __syncthreads();
        int ge = suffix_scan_p(s->hist, s->scan, s->wsum, tid);
        int gt = (tid < 255) ? s->scan[tid + 1] : 0;
        if (ge >= kkA && gt < kkA) { s->bbin = tid; s->bkk = kkA - gt; }
        if (same && ge >= kkB && gt < kkB) { s->bbin2 = tid; s->bkk2 = kkB - gt; }
        __syncthreads();
        if (!same) {
            s->hist[tid] = 0;
            __syncthreads();
            for (int i = tid; i < Hn; i += 256) {
                unsigned u = s->su[i];
                if ((u & mask) == prefB) atomicAdd(&s->hist[(u >> shift) & 255], 1);
            }
            __syncthreads();
            int ge2 = suffix_scan_p(s->hist, s->scan, s->wsum, tid);
            int gt2 = (tid < 255) ? s->scan[tid + 1] : 0;
            if (ge2 >= kkB && gt2 < kkB) { s->bbin2 = tid; s->bkk2 = kkB - gt2; }
            __syncthreads();
        }
        prefA |= ((unsigned)s->bbin) << shift;
        prefB |= ((unsigned)s->bbin2) << shift;
        kkA = s->bkk;
        kkB = s->bkk2;
        mask |= 0xFFu << shift;
    }
    *tA = prefA;
    *tB = prefB;
}

__global__ __launch_bounds__(256, 8)
void k_selaux(float* __restrict__ lataux, float* __restrict__ lat4k) {
    __shared__ SelShared s;
    __shared__ unsigned db[Hn / 32];
    const int r = blockIdx.x, tid = threadIdx.x;
    if (tid == 0) { s.cnt = 0; s.anylive = 0; }
    __syncthreads();
    // load dead-mask; detect whether ANY latent is live (dead1 bit set)
    unsigned myor = 0;
    for (int i = tid; i < Hn / 32; i += 256) {
        unsigned w = g_dead1[i];
        db[i] = w;
        myor |= w;
    }
    if (__any_sync(0xFFFFFFFFu, myor != 0))
        if ((tid & 31) == 0) s.anylive = 1;
    __syncthreads();

    float* oa = lataux + (size_t)r * Hn;
    float* o4 = lat4k  + (size_t)r * Hn;

    if (!s.anylive) {
        // masked input identically zero -> top-k outputs all zero after relu,
        // no hits (0 !> 1e-5), no compact entries (0 !> 0). Bit-identical.
        float4 z = {0.f, 0.f, 0.f, 0.f};
        for (int i = tid; i < Hn / 4; i += 256) {
            ((float4*)oa)[i] = z;
            ((float4*)o4)[i] = z;
        }
        if (tid == 0) g_acnt[r] = 0;
        return;
    }

    const float* row = g_pre + (size_t)r * Hn;
    for (int i = tid; i < Hn; i += 256) {
        float v  = row[i];
        float mv = ((db[i >> 5] >> (i & 31)) & 1u) ? v : 0.f;
        s.su[i] = fkey(mv);
    }
    __syncthreads();
    unsigned t512, t256;
    radix_kth2(&s, 512, 256, &t512, &t256);
    __syncthreads();
    for (int i = tid; i < Hn; i += 256) {
        unsigned u = s.su[i];
        float v = funkey(u);
        bool s5 = (u >= t512), s2 = (u >= t256);
        oa[i] = s5 ? fmaxf(v, 0.f) : 0.f;
        o4[i] = s2 ? fmaxf(v, 0.f) : 0.f;
        if (s2 && v > 1e-5f) g_hits2[i] = 1;
        if (s5 && v > 0.f) {
            int p = atomicAdd(&s.cnt, 1);
            if (p < MAXA) {
                g_aidx[(size_t)r * MAXA + p] = i | (s2 ? 0x10000 : 0);
                g_aval[(size_t)r * MAXA + p] = v;
            }
        }
    }
    __syncthreads();
    if (tid == 0) g_acnt[r] = (s.cnt < MAXA) ? s.cnt : MAXA;
}

__global__ void k_stats2(float* __restrict__ out_stats) {
    int h = blockIdx.x * 256 + threadIdx.x;
    int s2 = g_hits2[h] ? 1 : g_stats1[h] + 1;
    out_stats[h] = (float)s2;
    unsigned b = __ballot_sync(0xFFFFFFFFu, s2 > 30);
    if ((threadIdx.x & 31) == 0) g_dead12[h >> 5] = g_dead1[h >> 5] & b;
}

__global__ void k_prem2(float* __restrict__ out) {
    size_t i4 = (size_t)blockIdx.x * 256 + threadIdx.x;
    int h0 = (int)(i4 & (Hn / 4 - 1)) * 4;
    unsigned w = __ldg(&g_dead12[h0 >> 5]);
    float4 o;
    if (((w >> (h0 & 31)) & 0xFu) == 0u) {
        o.x = o.y = o.z = o.w = 0.f;
    } else {
        float4 p = ((const float4*)g_pre)[i4];
        o.x = ((w >> ((h0 & 31) + 0)) & 1u) ? p.x : 0.f;
        o.y = ((w >> ((h0 & 31) + 1)) & 1u) ? p.y : 0.f;
        o.z = ((w >> ((h0 & 31) + 2)) & 1u) ? p.z : 0.f;
        o.w = ((w >> ((h0 & 31) + 3)) & 1u) ? p.w : 0.f;
    }
    ((float4*)out)[i4] = o;
}

// ---------------------------------------------------------------------------
// decode_k: RECK + RECKPB from sel64's compact list only
// ---------------------------------------------------------------------------
__global__ void k_decode_k(const float* __restrict__ W,
                           const float* __restrict__ pb,
                           float* __restrict__ out) {
    __shared__ int   si[MAXK];
    __shared__ float sw[MAXK];
    const int r = blockIdx.x, tid = threadIdx.x;
    const int ck = g_kcnt[r];
    for (int i = tid; i < ck; i += 256) {
        si[i] = g_kidx[(size_t)r * MAXK + i];
        sw[i] = g_kval[(size_t)r * MAXK + i];
    }
    __syncthreads();

    const int c0 = tid * 4;
    float4 ak = {0, 0, 0, 0};
#pragma unroll 4
    for (int i = 0; i < ck; i++) {
        float v = sw[i];
        float4 w = *(const float4*)(W + (size_t)si[i] * Dn + c0);
        ak.x += v * w.x; ak.y += v * w.y; ak.z += v * w.z; ak.w += v * w.w;
    }

    float4 b = *(const float4*)(pb + c0);
    float4 rk, rkp;
    rk.x = ak.x + b.x; rk.y = ak.y + b.y; rk.z = ak.z + b.z; rk.w = ak.w + b.w;
    rkp.x = rk.x - b.x; rkp.y = rk.y - b.y; rkp.z = rk.z - b.z; rkp.w = rk.w - b.w;

    size_t o = (size_t)r * Dn + c0;
    *(float4*)(out + OFF_RECK   + o) = rk;
    *(float4*)(out + OFF_RECKPB + o) = rkp;
}

// ---------------------------------------------------------------------------
// decode_aux: REC4K + RECAUX from selaux's compact list
// (degenerate case ca=0 -> pure pre_bias broadcast)
// ---------------------------------------------------------------------------
__global__ void k_decode_aux(const float* __restrict__ W,
                             const float* __restrict__ pb,
                             float* __restrict__ out) {
    __shared__ int   si[MAXA];
    __shared__ float sw[MAXA];
    const int r = blockIdx.x, tid = threadIdx.x;
    const int ca = g_acnt[r];
    for (int i = tid; i < ca; i += 256) {
        si[i] = g_aidx[(size_t)r * MAXA + i];
        sw[i] = g_aval[(size_t)r * MAXA + i];
    }
    __syncthreads();

    const int c0 = tid * 4;
    float4 aa = {0, 0, 0, 0}, a4 = {0, 0, 0, 0};
#pragma unroll 4
    for (int i = 0; i < ca; i++) {
        int e = si[i];
        float v = sw[i];
        int h = e & 0xFFFF;
        float v4 = (e & 0x10000) ? v : 0.f;
        float4 w = *(const float4*)(W + (size_t)h * Dn + c0);
        aa.x += v * w.x;  aa.y += v * w.y;  aa.z += v * w.z;  aa.w += v * w.w;
        a4.x += v4 * w.x; a4.y += v4 * w.y; a4.z += v4 * w.z; a4.w += v4 * w.w;
    }

    float4 b = *(const float4*)(pb + c0);
    float4 r4, ra;
    r4.x = a4.x + b.x; r4.y = a4.y + b.y; r4.z = a4.z + b.z; r4.w = a4.w + b.w;
    ra.x = aa.x + b.x; ra.y = aa.y + b.y; ra.z = aa.z + b.z; ra.w = aa.w + b.w;

    size_t o = (size_t)r * Dn + c0;
    *(float4*)(out + OFF_REC4K  + o) = r4;
    *(float4*)(out + OFF_RECAUX + o) = ra;
}

// ---------------------------------------------------------------------------
extern "C" void kernel_launch(void* const* d_in, const int* in_sizes, int n_in,
                              void* d_out, int out_size) {
    const float* x     = (const float*)d_in[0];
    const float* pbias = (const float*)d_in[1];
    const float* W     = (const float*)d_in[2];
    const float* lb    = (const float*)d_in[3];
    const int*   stats = (const int*)d_in[4];
    float* out = (float*)d_out;

    // one-time setup (first call is the uncaptured correctness run)
    static cudaStream_t s2 = 0;
    static cudaEvent_t evK, evSA, evD;
    if (!s2) {
        cudaStreamCreateWithFlags(&s2, cudaStreamNonBlocking);
        cudaEventCreateWithFlags(&evK, cudaEventDisableTiming);
        cudaEventCreateWithFlags(&evSA, cudaEventDisableTiming);
        cudaEventCreateWithFlags(&evD, cudaEventDisableTiming);
        cudaFuncSetAttribute(k_mma, cudaFuncAttributeMaxDynamicSharedMemorySize,
                             NSTAGE * STAGE_B);
    }

    k_init<<<(Hn + 255) / 256, 256>>>();
    k_prepA<<<(Bn * Dn / 8) / 256, 256>>>(x, pbias, out + OFF_XB);
    k_prepB<<<(Hn * Dn / 8) / 256, 256>>>(W);

    dim3 gg(Hn / 128, Bn / 128);
    k_mma<<<gg, 256, NSTAGE * STAGE_B>>>(lb);

    k_sel64<<<Bn, 256>>>(out + OFF_LATK);
    k_stats1<<<Hn / 256, 256>>>(stats);

    // fork: decode_k on s2 (needs only sel64+stats1-era data)
    cudaEventRecord(evK, 0);
    cudaStreamWaitEvent(s2, evK, 0);
    k_decode_k<<<Bn, 256, 0, s2>>>(W, pbias, out);

    // main continues with the aux chain
    k_selaux<<<Bn, 256>>>(out + OFF_LATAUX, out + OFF_LAT4K);
    cudaEventRecord(evSA, 0);
    k_stats2<<<Hn / 256, 256>>>(out + OFF_STATS);
    k_prem2<<<(int)(((size_t)Bn * Hn / 4) / 256), 256>>>(out + OFF_PREM2);

    // decode_aux on s2 after selaux results are ready
    cudaStreamWaitEvent(s2, evSA, 0);
    k_decode_aux<<<Bn, 256, 0, s2>>>(W, pbias, out);
    cudaEventRecord(evD, s2);

    // join
    cudaStreamWaitEvent(0, evD, 0);
}

// round 17
// speedup vs baseline: 1.0164x; 1.0164x over previous
#include <cuda_runtime.h>
#include <cuda_fp16.h>
#include <math.h>

#define Bn 16384
#define Dn 1024
#define Hn 4096
#define MAXK 72
#define MAXA 544

// ---- output layout (elements, fp32) ----
static const size_t OFF_LATK   = 0ULL;
static const size_t OFF_XB     = (size_t)Bn * Hn;
static const size_t OFF_PREM2  = OFF_XB + (size_t)Bn * Dn;
static const size_t OFF_LAT4K  = OFF_PREM2 + (size_t)Bn * Hn;
static const size_t OFF_LATAUX = OFF_LAT4K + (size_t)Bn * Hn;
static const size_t OFF_RECK   = OFF_LATAUX + (size_t)Bn * Hn;
static const size_t OFF_REC4K  = OFF_RECK + (size_t)Bn * Dn;
static const size_t OFF_RECAUX = OFF_REC4K + (size_t)Bn * Dn;
static const size_t OFF_RECKPB = OFF_RECAUX + (size_t)Bn * Dn;
static const size_t OFF_STATS  = OFF_RECKPB + (size_t)Bn * Dn;

// ---- device scratch ----
__device__ float    g_pre[(size_t)Bn * Hn];       // 256 MB
__device__ int      g_hits1[Hn];
__device__ int      g_hits2[Hn];
__device__ int      g_stats1[Hn];
__device__ unsigned g_dead1[Hn / 32];
__device__ unsigned g_dead12[Hn / 32];

// fp16 limb matrices, row-major. limb1 scaled by 2^11 (normal range)
__device__ __align__(16) half gA0[(size_t)Bn * Dn];   // 32 MB
__device__ __align__(16) half gA1[(size_t)Bn * Dn];
__device__ __align__(16) half gB0[(size_t)Hn * Dn];   // 8 MB
__device__ __align__(16) half gB1[(size_t)Hn * Dn];

#define LIMB_SCALE 2048.0f
#define LIMB_INV   (1.0f / 2048.0f)

__device__ __forceinline__ unsigned fkey(float f) {
    unsigned u = __float_as_uint(f);
    return (u & 0x80000000u) ? ~u : (u | 0x80000000u);
}
__device__ __forceinline__ float funkey(unsigned k) {
    unsigned u = (k & 0x80000000u) ? (k ^ 0x80000000u) : ~k;
    return __uint_as_float(u);
}
__device__ __forceinline__ unsigned smem_u32(const void* p) {
    unsigned a;
    asm("{ .reg .u64 t; cvta.to.shared.u64 t, %1; cvt.u32.u64 %0, t; }" : "=r"(a) : "l"(p));
    return a;
}

// ---------------------------------------------------------------------------
__global__ void k_init() {
    int i = blockIdx.x * 256 + threadIdx.x;
    if (i < Hn) { g_hits1[i] = 0; g_hits2[i] = 0; }
}

// ---------------------------------------------------------------------------
// prepA: xb = x - pre_bias (output) + fp16 2-limb decomposition (limb1 * 2^11)
// ---------------------------------------------------------------------------
__global__ void k_prepA(const float* __restrict__ x, const float* __restrict__ pb,
                        float* __restrict__ xb_out) {
    unsigned g  = blockIdx.x * 256 + threadIdx.x;   // Bn*Dn/8 units of 8 elems
    unsigned kc = g & 127;
    size_t base = (size_t)g * 8;
    float v[8];
    float4 x0 = *(const float4*)(x + base);
    float4 x1 = *(const float4*)(x + base + 4);
    float4 p0 = *(const float4*)(pb + kc * 8);
    float4 p1 = *(const float4*)(pb + kc * 8 + 4);
    v[0] = x0.x - p0.x; v[1] = x0.y - p0.y; v[2] = x0.z - p0.z; v[3] = x0.w - p0.w;
    v[4] = x1.x - p1.x; v[5] = x1.y - p1.y; v[6] = x1.z - p1.z; v[7] = x1.w - p1.w;
    *(float4*)(xb_out + base)     = make_float4(v[0], v[1], v[2], v[3]);
    *(float4*)(xb_out + base + 4) = make_float4(v[4], v[5], v[6], v[7]);

    half h0[8], h1[8];
#pragma unroll
    for (int i = 0; i < 8; i++) {
        h0[i] = __float2half_rn(v[i]);
        h1[i] = __float2half_rn((v[i] - __half2float(h0[i])) * LIMB_SCALE);
    }
    *(uint4*)(gA0 + base) = *(const uint4*)h0;
    *(uint4*)(gA1 + base) = *(const uint4*)h1;
}

// ---------------------------------------------------------------------------
// prepB: W fp16 2-limb decomposition (limb1 * 2^11)
// ---------------------------------------------------------------------------
__global__ void k_prepB(const float* __restrict__ W) {
    unsigned g  = blockIdx.x * 256 + threadIdx.x;   // Hn*Dn/8
    size_t base = (size_t)g * 8;
    float v[8];
    float4 x0 = *(const float4*)(W + base);
    float4 x1 = *(const float4*)(W + base + 4);
    v[0] = x0.x; v[1] = x0.y; v[2] = x0.z; v[3] = x0.w;
    v[4] = x1.x; v[5] = x1.y; v[6] = x1.z; v[7] = x1.w;
    half h0[8], h1[8];
#pragma unroll
    for (int i = 0; i < 8; i++) {
        h0[i] = __float2half_rn(v[i]);
        h1[i] = __float2half_rn((v[i] - __half2float(h0[i])) * LIMB_SCALE);
    }
    *(uint4*)(gB0 + base) = *(const uint4*)h0;
    *(uint4*)(gB1 + base) = *(const uint4*)h1;
}

// ---------------------------------------------------------------------------
// HMMA GEMM: pre = xb @ W^T + latent_bias   (frozen: at mma.sync HW rate)
// ---------------------------------------------------------------------------
#define BK 32
#define NSTAGE 5
#define STAGE_B 40960
#define SLAB_B 10240
#define NCH (Dn / BK)

__device__ __forceinline__ void ldsm_x4(unsigned* r, unsigned addr) {
    asm volatile("ldmatrix.sync.aligned.m8n8.x4.shared.b16 {%0,%1,%2,%3}, [%4];"
                 : "=r"(r[0]), "=r"(r[1]), "=r"(r[2]), "=r"(r[3]) : "r"(addr));
}
__device__ __forceinline__ void ldsm_x2(unsigned* r, unsigned addr) {
    asm volatile("ldmatrix.sync.aligned.m8n8.x2.shared.b16 {%0,%1}, [%2];"
                 : "=r"(r[0]), "=r"(r[1]) : "r"(addr));
}
__device__ __forceinline__ void mma16816(float* c, const unsigned* a, const unsigned* b) {
    asm volatile("mma.sync.aligned.m16n8k16.row.col.f32.f16.f16.f32 "
                 "{%0,%1,%2,%3},{%4,%5,%6,%7},{%8,%9},{%0,%1,%2,%3};"
                 : "+f"(c[0]), "+f"(c[1]), "+f"(c[2]), "+f"(c[3])
                 : "r"(a[0]), "r"(a[1]), "r"(a[2]), "r"(a[3]), "r"(b[0]), "r"(b[1]));
}

__global__ __launch_bounds__(256, 1)
void k_mma(const float* __restrict__ lb) {
    extern __shared__ __align__(16) char smem[];
    const unsigned sb = smem_u32(smem);
    const int tid = threadIdx.x;
    const int wid = tid >> 5, lane = tid & 31;
    const int brow = blockIdx.y * 128, bcol = blockIdx.x * 128;
    const int wm = (wid >> 2) * 64, wn = (wid & 3) * 32;

    float c0[4][4][4], c1[4][4][4];
#pragma unroll
    for (int i = 0; i < 4; i++)
#pragma unroll
        for (int j = 0; j < 4; j++)
#pragma unroll
            for (int q = 0; q < 4; q++) { c0[i][j][q] = 0.f; c1[i][j][q] = 0.f; }

    const int r = tid >> 1, ub = (tid & 1) * 2;
    const half* sA0 = gA0 + (size_t)(brow + r) * Dn + ub * 8;
    const half* sA1 = gA1 + (size_t)(brow + r) * Dn + ub * 8;
    const half* sB0 = gB0 + (size_t)(bcol + r) * Dn + ub * 8;
    const half* sB1 = gB1 + (size_t)(bcol + r) * Dn + ub * 8;
    const unsigned dstb = r * 80 + ub * 16;

    auto ld_stage = [&](int c, int s) {
        unsigned d = sb + s * STAGE_B + dstb;
        const int co = c * BK;
        asm volatile("cp.async.cg.shared.global [%0], [%1], 16;" :: "r"(d),                  "l"(sA0 + co));
        asm volatile("cp.async.cg.shared.global [%0], [%1], 16;" :: "r"(d + 16),             "l"(sA0 + co + 8));
        asm volatile("cp.async.cg.shared.global [%0], [%1], 16;" :: "r"(d + SLAB_B),         "l"(sA1 + co));
        asm volatile("cp.async.cg.shared.global [%0], [%1], 16;" :: "r"(d + SLAB_B + 16),    "l"(sA1 + co + 8));
        asm volatile("cp.async.cg.shared.global [%0], [%1], 16;" :: "r"(d + 2 * SLAB_B),     "l"(sB0 + co));
        asm volatile("cp.async.cg.shared.global [%0], [%1], 16;" :: "r"(d + 2 * SLAB_B + 16),"l"(sB0 + co + 8));
        asm volatile("cp.async.cg.shared.global [%0], [%1], 16;" :: "r"(d + 3 * SLAB_B),     "l"(sB1 + co));
        asm volatile("cp.async.cg.shared.global [%0], [%1], 16;" :: "r"(d + 3 * SLAB_B + 16),"l"(sB1 + co + 8));
        asm volatile("cp.async.commit_group;" ::: "memory");
    };

    ld_stage(0, 0); ld_stage(1, 1); ld_stage(2, 2); ld_stage(3, 3);

    const unsigned aoff = (wm + (lane & 15)) * 80 + (lane >> 4) * 16;
    const unsigned boff = (wn + (lane & 7)) * 80 + ((lane >> 3) & 1) * 16;

    for (int ch = 0; ch < NCH; ch++) {
        int s = ch % NSTAGE;
        asm volatile("cp.async.wait_group 3;" ::: "memory");
        __syncthreads();
        if (ch + 4 < NCH) ld_stage(ch + 4, (ch + 4) % NSTAGE);
        else asm volatile("cp.async.commit_group;" ::: "memory");

        unsigned sbase = sb + s * STAGE_B;
#pragma unroll
        for (int ks = 0; ks < 2; ks++) {
            unsigned kb = ks * 32;
            unsigned a0f[4][4], a1f[4][4], b0f[4][2], b1f[4][2];
#pragma unroll
            for (int mf = 0; mf < 4; mf++) {
                unsigned ad = sbase + aoff + mf * (16 * 80) + kb;
                ldsm_x4(a0f[mf], ad);
                ldsm_x4(a1f[mf], ad + SLAB_B);
            }
#pragma unroll
            for (int nf = 0; nf < 4; nf++) {
                unsigned bd = sbase + 2 * SLAB_B + boff + nf * (8 * 80) + kb;
                ldsm_x2(b0f[nf], bd);
                ldsm_x2(b1f[nf], bd + SLAB_B);
            }
#pragma unroll
            for (int mf = 0; mf < 4; mf++)
#pragma unroll
                for (int nf = 0; nf < 4; nf++) {
                    mma16816(c0[mf][nf], a0f[mf], b0f[nf]);
                    mma16816(c1[mf][nf], a0f[mf], b1f[nf]);
                    mma16816(c1[mf][nf], a1f[mf], b0f[nf]);
                }
        }
    }

#pragma unroll
    for (int mf = 0; mf < 4; mf++) {
        int row0 = brow + wm + mf * 16 + (lane >> 2);
#pragma unroll
        for (int nf = 0; nf < 4; nf++) {
            int col = bcol + wn + nf * 8 + (lane & 3) * 2;
            float2 bv = *(const float2*)(lb + col);
            float2 v0, v1;
            v0.x = fmaf(c1[mf][nf][0], LIMB_INV, c0[mf][nf][0]) + bv.x;
            v0.y = fmaf(c1[mf][nf][1], LIMB_INV, c0[mf][nf][1]) + bv.y;
            v1.x = fmaf(c1[mf][nf][2], LIMB_INV, c0[mf][nf][2]) + bv.x;
            v1.y = fmaf(c1[mf][nf][3], LIMB_INV, c0[mf][nf][3]) + bv.y;
            *(float2*)(g_pre + (size_t)row0 * Hn + col)       = v0;
            *(float2*)(g_pre + (size_t)(row0 + 8) * Hn + col) = v1;
        }
    }
}

// ---------------------------------------------------------------------------
// suffix scan over a 256-bin histogram (warp shuffles, 2 barriers)
// ---------------------------------------------------------------------------
__device__ __forceinline__ int suffix_scan_p(int* hist, int* scan, int* wsum, int tid) {
    int w = tid >> 5, lane = tid & 31;
    int v = hist[tid];
#pragma unroll
    for (int off = 1; off < 32; off <<= 1) {
        int o = __shfl_down_sync(0xFFFFFFFFu, v, off);
        if (lane + off < 32) v += o;
    }
    if (lane == 0) wsum[w] = v;
    __syncthreads();
    int carry = 0;
#pragma unroll
    for (int w2 = 1; w2 < 8; w2++) carry += (w2 > w) ? wsum[w2] : 0;
    int ge = v + carry;
    scan[tid] = ge;
    __syncthreads();
    return ge;
}

// ---------------------------------------------------------------------------
// sel64 + fused decode_k: registers radix select, then inline W-gather
// writes latk, hits1, RECK, RECKPB
// ---------------------------------------------------------------------------
struct Sel64Shared {
    int hist[256];
    int scan[256];
    int wsum[8];
    int bbin, bkk, cnt;
    int   si[MAXK];
    float sv[MAXK];
};

__global__ __launch_bounds__(256, 5)
void k_sel64_dec(float* __restrict__ latk,
                 const float* __restrict__ W,
                 const float* __restrict__ pb,
                 float* __restrict__ out) {
    __shared__ Sel64Shared s;
    const int r = blockIdx.x, tid = threadIdx.x;
    const float* row = g_pre + (size_t)r * Hn;

    unsigned k[16];
#pragma unroll
    for (int j = 0; j < 16; j++) k[j] = fkey(row[tid + j * 256]);
    if (tid == 0) s.cnt = 0;

    unsigned prefix = 0, mask = 0;
    int kk = 64;
#pragma unroll
    for (int shift = 24; shift >= 0; shift -= 8) {
        s.hist[tid] = 0;
        __syncthreads();
#pragma unroll
        for (int j = 0; j < 16; j++) {
            unsigned u = k[j];
            if ((u & mask) == prefix) atomicAdd(&s.hist[(u >> shift) & 255], 1);
        }
        __syncthreads();
        int ge = suffix_scan_p(s.hist, s.scan, s.wsum, tid);
        int gt = (tid < 255) ? s.scan[tid + 1] : 0;
        if (ge >= kk && gt < kk) { s.bbin = tid; s.bkk = kk - gt; }
        __syncthreads();
        prefix |= ((unsigned)s.bbin) << shift;
        mask   |= 0xFFu << shift;
        kk = s.bkk;
    }
    const unsigned t64 = prefix;

    float* orow = latk + (size_t)r * Hn;
#pragma unroll
    for (int j = 0; j < 16; j++) {
        int i = tid + j * 256;
        unsigned u = k[j];
        bool sel = (u >= t64);
        float v = funkey(u);
        orow[i] = sel ? fmaxf(v, 0.f) : 0.f;
        if (sel) {
            if (v > 1e-5f) g_hits1[i] = 1;
            if (v > 0.f) {
                int p = atomicAdd(&s.cnt, 1);
                if (p < MAXK) { s.si[p] = i; s.sv[p] = v; }
            }
        }
    }
    __syncthreads();

    // fused decode_k: RECK = sum v*W[h] + pb ; RECKPB = RECK - pb
    const int ck = (s.cnt < MAXK) ? s.cnt : MAXK;
    const int c0 = tid * 4;
    float4 ak = {0, 0, 0, 0};
#pragma unroll 4
    for (int i = 0; i < ck; i++) {
        float v = s.sv[i];
        float4 w = *(const float4*)(W + (size_t)s.si[i] * Dn + c0);
        ak.x += v * w.x; ak.y += v * w.y; ak.z += v * w.z; ak.w += v * w.w;
    }
    float4 b = *(const float4*)(pb + c0);
    float4 rk, rkp;
    rk.x = ak.x + b.x; rk.y = ak.y + b.y; rk.z = ak.z + b.z; rk.w = ak.w + b.w;
    rkp.x = rk.x - b.x; rkp.y = rk.y - b.y; rkp.z = rk.z - b.z; rkp.w = rk.w - b.w;
    size_t o = (size_t)r * Dn + c0;
    *(float4*)(out + OFF_RECK   + o) = rk;
    *(float4*)(out + OFF_RECKPB + o) = rkp;
}

__global__ void k_stats1(const int* __restrict__ stats_in) {
    int h = blockIdx.x * 256 + threadIdx.x;
    int s1 = g_hits1[h] ? 1 : stats_in[h] + 1;
    g_stats1[h] = s1;
    unsigned b = __ballot_sync(0xFFFFFFFFu, s1 > 30);
    if ((threadIdx.x & 31) == 0) g_dead1[h >> 5] = b;
}

// ---------------------------------------------------------------------------
// selaux + fused decode_aux (fast path: zero-fill + pb broadcast)
// ---------------------------------------------------------------------------
struct SelShared {
    unsigned su[Hn];
    int hist[256];
    int scan[256];
    int wsum[8];
    int bbin, bkk, bbin2, bkk2, cnt, anylive;
    int   si[MAXA];
    float sv[MAXA];
};

__device__ void radix_kth2(SelShared* s, int kA0, int kB0,
                           unsigned* tA, unsigned* tB) {
    const int tid = threadIdx.x;
    unsigned prefA = 0, prefB = 0, mask = 0;
    int kkA = kA0, kkB = kB0;
#pragma unroll
    for (int shift = 24; shift >= 0; shift -= 8) {
        bool same = (prefA == prefB);
        s->hist[tid] = 0;
        __syncthreads();
        for (int i = tid; i < Hn; i += 256) {
            unsigned u = s->su[i];
            if ((u & mask) == prefA) atomicAdd(&s->hist[(u >> shift) & 255], 1);
        }
        __syncthreads();
        int ge = suffix_scan_p(s->hist, s->scan, s->wsum, tid);
        int gt = (tid < 255) ? s->scan[tid + 1] : 0;
        if (ge >= kkA && gt < kkA) { s->bbin = tid; s->bkk = kkA - gt; }
        if (same && ge >= kkB && gt < kkB) { s->bbin2 = tid; s->bkk2 = kkB - gt; }
        __syncthreads();
        if (!same) {
            s->hist[tid] = 0;
            __syncthreads();
            for (int i = tid; i < Hn; i += 256) {
                unsigned u = s->su[i];
                if ((u & mask) == prefB) atomicAdd(&s->hist[(u >> shift) & 255], 1);
            }
            __syncthreads();
            int ge2 = suffix_scan_p(s->hist, s->scan, s->wsum, tid);
            int gt2 = (tid < 255) ? s->scan[tid + 1] : 0;
            if (ge2 >= kkB && gt2 < kkB) { s->bbin2 = tid; s->bkk2 = kkB - gt2; }
            __syncthreads();
        }
        prefA |= ((unsigned)s->bbin) << shift;
        prefB |= ((unsigned)s->bbin2) << shift;
        kkA = s->bkk;
        kkB = s->bkk2;
        mask |= 0xFFu << shift;
    }
    *tA = prefA;
    *tB = prefB;
}

__global__ __launch_bounds__(256, 4)
void k_selaux_dec(float* __restrict__ lataux, float* __restrict__ lat4k,
                  const float* __restrict__ W, const float* __restrict__ pb,
                  float* __restrict__ out) {
    __shared__ SelShared s;
    __shared__ unsigned db[Hn / 32];
    const int r = blockIdx.x, tid = threadIdx.x;
    if (tid == 0) { s.cnt = 0; s.anylive = 0; }
    __syncthreads();
    unsigned myor = 0;
    for (int i = tid; i < Hn / 32; i += 256) {
        unsigned w = g_dead1[i];
        db[i] = w;
        myor |= w;
    }
    if (__any_sync(0xFFFFFFFFu, myor != 0))
        if ((tid & 31) == 0) s.anylive = 1;
    __syncthreads();

    float* oa = lataux + (size_t)r * Hn;
    float* o4 = lat4k  + (size_t)r * Hn;
    const int c0 = tid * 4;
    const size_t od = (size_t)r * Dn + c0;

    if (!s.anylive) {
        // masked input identically zero -> outputs all zero; decode = pb broadcast
        float4 z = {0.f, 0.f, 0.f, 0.f};
        for (int i = tid; i < Hn / 4; i += 256) {
            ((float4*)oa)[i] = z;
            ((float4*)o4)[i] = z;
        }
        float4 b = *(const float4*)(pb + c0);
        *(float4*)(out + OFF_REC4K  + od) = b;
        *(float4*)(out + OFF_RECAUX + od) = b;
        return;
    }

    const float* row = g_pre + (size_t)r * Hn;
    for (int i = tid; i < Hn; i += 256) {
        float v  = row[i];
        float mv = ((db[i >> 5] >> (i & 31)) & 1u) ? v : 0.f;
        s.su[i] = fkey(mv);
    }
    __syncthreads();
    unsigned t512, t256;
    radix_kth2(&s, 512, 256, &t512, &t256);
    __syncthreads();
    for (int i = tid; i < Hn; i += 256) {
        unsigned u = s.su[i];
        float v = funkey(u);
        bool s5 = (u >= t512), s2 = (u >= t256);
        oa[i] = s5 ? fmaxf(v, 0.f) : 0.f;
        o4[i] = s2 ? fmaxf(v, 0.f) : 0.f;
        if (s2 && v > 1e-5f) g_hits2[i] = 1;
        if (s5 && v > 0.f) {
            int p = atomicAdd(&s.cnt, 1);
            if (p < MAXA) {
                s.si[p] = i | (s2 ? 0x10000 : 0);
                s.sv[p] = v;
            }
        }
    }
    __syncthreads();

    // fused decode_aux
    const int ca = (s.cnt < MAXA) ? s.cnt : MAXA;
    float4 aa = {0, 0, 0, 0}, a4 = {0, 0, 0, 0};
#pragma unroll 4
    for (int i = 0; i < ca; i++) {
        int e = s.si[i];
        float v = s.sv[i];
        int h = e & 0xFFFF;
        float v4 = (e & 0x10000) ? v : 0.f;
        float4 w = *(const float4*)(W + (size_t)h * Dn + c0);
        aa.x += v * w.x;  aa.y += v * w.y;  aa.z += v * w.z;  aa.w += v * w.w;
        a4.x += v4 * w.x; a4.y += v4 * w.y; a4.z += v4 * w.z; a4.w += v4 * w.w;
    }
    float4 b = *(const float4*)(pb + c0);
    float4 r4, ra;
    r4.x = a4.x + b.x; r4.y = a4.y + b.y; r4.z = a4.z + b.z; r4.w = a4.w + b.w;
    ra.x = aa.x + b.x; ra.y = aa.y + b.y; ra.z = aa.z + b.z; ra.w = aa.w + b.w;
    *(float4*)(out + OFF_REC4K  + od) = r4;
    *(float4*)(out + OFF_RECAUX + od) = ra;
}

__global__ void k_stats2(float* __restrict__ out_stats) {
    int h = blockIdx.x * 256 + threadIdx.x;
    int s2 = g_hits2[h] ? 1 : g_stats1[h] + 1;
    out_stats[h] = (float)s2;
    unsigned b = __ballot_sync(0xFFFFFFFFu, s2 > 30);
    if ((threadIdx.x & 31) == 0) g_dead12[h >> 5] = g_dead1[h >> 5] & b;
}

__global__ void k_prem2(float* __restrict__ out) {
    size_t i4 = (size_t)blockIdx.x * 256 + threadIdx.x;
    int h0 = (int)(i4 & (Hn / 4 - 1)) * 4;
    unsigned w = __ldg(&g_dead12[h0 >> 5]);
    float4 o;
    if (((w >> (h0 & 31)) & 0xFu) == 0u) {
        o.x = o.y = o.z = o.w = 0.f;
    } else {
        float4 p = ((const float4*)g_pre)[i4];
        o.x = ((w >> ((h0 & 31) + 0)) & 1u) ? p.x : 0.f;
        o.y = ((w >> ((h0 & 31) + 1)) & 1u) ? p.y : 0.f;
        o.z = ((w >> ((h0 & 31) + 2)) & 1u) ? p.z : 0.f;
        o.w = ((w >> ((h0 & 31) + 3)) & 1u) ? p.w : 0.f;
    }
    ((float4*)out)[i4] = o;
}

// ---------------------------------------------------------------------------
extern "C" void kernel_launch(void* const* d_in, const int* in_sizes, int n_in,
                              void* d_out, int out_size) {
    const float* x     = (const float*)d_in[0];
    const float* pbias = (const float*)d_in[1];
    const float* W     = (const float*)d_in[2];
    const float* lb    = (const float*)d_in[3];
    const int*   stats = (const int*)d_in[4];
    float* out = (float*)d_out;

    cudaFuncSetAttribute(k_mma, cudaFuncAttributeMaxDynamicSharedMemorySize,
                         NSTAGE * STAGE_B);

    k_init<<<(Hn + 255) / 256, 256>>>();
    k_prepA<<<(Bn * Dn / 8) / 256, 256>>>(x, pbias, out + OFF_XB);
    k_prepB<<<(Hn * Dn / 8) / 256, 256>>>(W);

    dim3 gg(Hn / 128, Bn / 128);
    k_mma<<<gg, 256, NSTAGE * STAGE_B>>>(lb);

    k_sel64_dec<<<Bn, 256>>>(out + OFF_LATK, W, pbias, out);
    k_stats1<<<Hn / 256, 256>>>(stats);
    k_selaux_dec<<<Bn, 256>>>(out + OFF_LATAUX, out + OFF_LAT4K, W, pbias, out);
    k_stats2<<<Hn / 256, 256>>>(out + OFF_STATS);
    k_prem2<<<(int)(((size_t)Bn * Hn / 4) / 256), 256>>>(out + OFF_PREM2);
}